// round 1
// baseline (speedup 1.0000x reference)
#include <cuda_runtime.h>
#include <cuda_bf16.h>

// Problem constants (fixed by the dataset)
#define NN 100000
#define EE 1600000
#define HH 32

#define CDIV(a, b) (((a) + (b) - 1) / (b))

// Scratch (static device globals; no allocation allowed)
__device__ float g_dinv[NN];        // degree -> rsqrt(degree)
__device__ float g_norm[EE];        // per-edge symmetric norm
__device__ float g_h0[NN * HH];     // ping
__device__ float g_h1[NN * HH];     // pong
__device__ float g_t[NN * HH];      // transformed features (h @ W)

__device__ __forceinline__ float* hbuf(int s) { return s ? g_h1 : g_h0; }

// ---------------------------------------------------------------------------
// Encoder: per-node 2-layer MLP. fan_in = 3 (boundary: x0,x1,y) or 2 (interior).
// h0[node] = relu( relu(feat@W1 + b1) @ W2 + b2 );  also init deg (self loop).
// ---------------------------------------------------------------------------
__global__ void enc_kernel(const float* __restrict__ x, const float* __restrict__ y,
                           const int* __restrict__ idx, int n, int fan_in,
                           const float* __restrict__ W1, const float* __restrict__ b1,
                           const float* __restrict__ W2, const float* __restrict__ b2) {
    __shared__ float sW1[3 * 32], sb1[32], sW2[32 * 32], sb2[32];
    int t = threadIdx.x;
    for (int i = t; i < fan_in * 32; i += blockDim.x) sW1[i] = W1[i];
    for (int i = t; i < 32; i += blockDim.x) { sb1[i] = b1[i]; sb2[i] = b2[i]; }
    for (int i = t; i < 1024; i += blockDim.x) sW2[i] = W2[i];
    __syncthreads();

    int j = blockIdx.x * blockDim.x + t;
    if (j >= n) return;
    int node = idx[j];
    float f0 = x[2 * node], f1 = x[2 * node + 1];
    float f2 = (fan_in == 3) ? y[node] : 0.0f;

    float hid[32];
#pragma unroll
    for (int k = 0; k < 32; k++) {
        float a = f0 * sW1[k] + f1 * sW1[32 + k] + sb1[k];
        if (fan_in == 3) a += f2 * sW1[64 + k];
        hid[k] = fmaxf(a, 0.0f);
    }
    float acc[32];
#pragma unroll
    for (int jj = 0; jj < 32; jj++) acc[jj] = sb2[jj];
#pragma unroll
    for (int k = 0; k < 32; k++) {
        float hk = hid[k];
#pragma unroll
        for (int jj = 0; jj < 32; jj++) acc[jj] += hk * sW2[k * 32 + jj];
    }
    float4* hp = (float4*)&g_h0[node * HH];
#pragma unroll
    for (int q = 0; q < 8; q++) {
        hp[q] = make_float4(fmaxf(acc[4 * q + 0], 0.0f), fmaxf(acc[4 * q + 1], 0.0f),
                            fmaxf(acc[4 * q + 2], 0.0f), fmaxf(acc[4 * q + 3], 0.0f));
    }
    g_dinv[node] = 1.0f;  // self-loop contribution to degree
}

// Degree accumulation: deg[dst] += 1 per edge (float adds of 1.0 are exact).
__global__ void deg_kernel(const int* __restrict__ dst) {
    int e = blockIdx.x * blockDim.x + threadIdx.x;
    if (e < EE) atomicAdd(&g_dinv[dst[e]], 1.0f);
}

__global__ void dinv_kernel() {
    int i = blockIdx.x * blockDim.x + threadIdx.x;
    if (i < NN) g_dinv[i] = rsqrtf(g_dinv[i]);  // deg >= 1 always (self loop)
}

__global__ void norm_kernel(const int* __restrict__ src, const int* __restrict__ dst) {
    int e = blockIdx.x * blockDim.x + threadIdx.x;
    if (e < EE) g_norm[e] = g_dinv[src[e]] * g_dinv[dst[e]];
}

// ---------------------------------------------------------------------------
// Dense transform for one GCN layer. Per node i:
//   v = relu(hin[i])                      (relu is identity on conv-1 input)
//   t[i] = v @ W
//   hout[i] = t[i] * dinv[i]^2 + b        (self-loop term + bias; edges add later)
// ---------------------------------------------------------------------------
__global__ void xform_kernel(int in_sel, int out_sel,
                             const float* __restrict__ W, const float* __restrict__ b) {
    __shared__ float sW[1024], sb[32];
    int t = threadIdx.x;
    for (int i = t; i < 1024; i += blockDim.x) sW[i] = W[i];
    for (int i = t; i < 32; i += blockDim.x) sb[i] = b[i];
    __syncthreads();

    int i = blockIdx.x * blockDim.x + t;
    if (i >= NN) return;
    const float* hin = hbuf(in_sel);
    float* hout = hbuf(out_sel);

    float acc[32];
#pragma unroll
    for (int jj = 0; jj < 32; jj++) acc[jj] = 0.0f;

    const float4* hp = (const float4*)(hin + i * HH);
#pragma unroll
    for (int q = 0; q < 8; q++) {
        float4 v4 = hp[q];
        float vv[4] = {fmaxf(v4.x, 0.0f), fmaxf(v4.y, 0.0f), fmaxf(v4.z, 0.0f), fmaxf(v4.w, 0.0f)};
#pragma unroll
        for (int r = 0; r < 4; r++) {
            float v = vv[r];
            int k = 4 * q + r;
#pragma unroll
            for (int jj = 0; jj < 32; jj++) acc[jj] += v * sW[k * 32 + jj];
        }
    }
    float di = g_dinv[i];
    float sl = di * di;
    float4* tp = (float4*)&g_t[i * HH];
    float4* op = (float4*)&hout[i * HH];
#pragma unroll
    for (int q = 0; q < 8; q++) {
        float4 a = make_float4(acc[4 * q], acc[4 * q + 1], acc[4 * q + 2], acc[4 * q + 3]);
        tp[q] = a;
        op[q] = make_float4(a.x * sl + sb[4 * q], a.y * sl + sb[4 * q + 1],
                            a.z * sl + sb[4 * q + 2], a.w * sl + sb[4 * q + 3]);
    }
}

// ---------------------------------------------------------------------------
// Edge scatter: 8 threads per edge, each handles one float4 chunk.
//   hout[dst] += t[src] * norm[e]   via 128-bit vector atomicAdd (RED.128).
// ---------------------------------------------------------------------------
__global__ void scatter_kernel(const int* __restrict__ src, const int* __restrict__ dst,
                               int out_sel) {
    long long gid = (long long)blockIdx.x * blockDim.x + threadIdx.x;
    if (gid >= (long long)EE * 8) return;
    int e = (int)(gid >> 3);
    int c = (int)(gid & 7);
    int s = __ldg(src + e);
    int d = __ldg(dst + e);
    float nrm = __ldg(g_norm + e);
    const float4* tp = (const float4*)g_t;
    float4 v = __ldg(tp + (long long)s * 8 + c);
    float4 m = make_float4(v.x * nrm, v.y * nrm, v.z * nrm, v.w * nrm);
    float4* out4 = (float4*)hbuf(out_sel);
    atomicAdd(out4 + (long long)d * 8 + c, m);  // sm_90+: 128-bit red.add
}

// Head: out[i] = dot(relu(h[i]), Wf) + bf
__global__ void final_kernel(int in_sel, const float* __restrict__ Wf,
                             const float* __restrict__ bf, float* __restrict__ out) {
    __shared__ float sw[32];
    __shared__ float sbf;
    int t = threadIdx.x;
    if (t < 32) sw[t] = Wf[t];
    if (t == 0) sbf = bf[0];
    __syncthreads();

    int i = blockIdx.x * blockDim.x + t;
    if (i >= NN) return;
    const float4* hp = (const float4*)(hbuf(in_sel) + i * HH);
    float acc = sbf;
#pragma unroll
    for (int q = 0; q < 8; q++) {
        float4 v = hp[q];
        acc += fmaxf(v.x, 0.0f) * sw[4 * q + 0];
        acc += fmaxf(v.y, 0.0f) * sw[4 * q + 1];
        acc += fmaxf(v.z, 0.0f) * sw[4 * q + 2];
        acc += fmaxf(v.w, 0.0f) * sw[4 * q + 3];
    }
    out[i] = acc;
}

extern "C" void kernel_launch(void* const* d_in, const int* in_sizes, int n_in,
                              void* d_out, int out_size) {
    const float* x    = (const float*)d_in[0];
    const float* y    = (const float*)d_in[1];
    const int*   ei   = (const int*)d_in[2];
    const int*   bidx = (const int*)d_in[3];
    const int*   iidx = (const int*)d_in[4];
    const float* Wb1 = (const float*)d_in[5];
    const float* bb1 = (const float*)d_in[6];
    const float* Wb2 = (const float*)d_in[7];
    const float* bb2 = (const float*)d_in[8];
    const float* Wi1 = (const float*)d_in[9];
    const float* bi1 = (const float*)d_in[10];
    const float* Wi2 = (const float*)d_in[11];
    const float* bi2 = (const float*)d_in[12];
    const float* Wc1 = (const float*)d_in[13];
    const float* bc1 = (const float*)d_in[14];
    const float* Wc2 = (const float*)d_in[15];
    const float* bc2 = (const float*)d_in[16];
    const float* Wc3 = (const float*)d_in[17];
    const float* bc3 = (const float*)d_in[18];
    const float* Wf  = (const float*)d_in[19];
    const float* bf  = (const float*)d_in[20];

    int NB = in_sizes[3];
    int NI = in_sizes[4];
    const int* src = ei;        // edge_index[0,:]
    const int* dst = ei + EE;   // edge_index[1,:]

    // Encoders (also init deg = 1.0 for every node: boundary U interior = all)
    enc_kernel<<<CDIV(NB, 128), 128>>>(x, y, bidx, NB, 3, Wb1, bb1, Wb2, bb2);
    enc_kernel<<<CDIV(NI, 128), 128>>>(x, y, iidx, NI, 2, Wi1, bi1, Wi2, bi2);

    // Degree / norm precompute
    deg_kernel<<<CDIV(EE, 256), 256>>>(dst);
    dinv_kernel<<<CDIV(NN, 256), 256>>>();
    norm_kernel<<<CDIV(EE, 256), 256>>>(src, dst);

    // Conv 1: h0 -> h1
    xform_kernel<<<CDIV(NN, 128), 128>>>(0, 1, Wc1, bc1);
    scatter_kernel<<<CDIV((long long)EE * 8, 256), 256>>>(src, dst, 1);
    // Conv 2: h1 -> h0
    xform_kernel<<<CDIV(NN, 128), 128>>>(1, 0, Wc2, bc2);
    scatter_kernel<<<CDIV((long long)EE * 8, 256), 256>>>(src, dst, 0);
    // Conv 3: h0 -> h1
    xform_kernel<<<CDIV(NN, 128), 128>>>(0, 1, Wc3, bc3);
    scatter_kernel<<<CDIV((long long)EE * 8, 256), 256>>>(src, dst, 1);

    // Head
    final_kernel<<<CDIV(NN, 256), 256>>>(1, Wf, bf, (float*)d_out);
}

// round 2
// speedup vs baseline: 1.1590x; 1.1590x over previous
#include <cuda_runtime.h>
#include <cuda_bf16.h>

// Problem constants (fixed by the dataset)
#define NN 100000
#define EE 1600000
#define HH 32
#define SCAN_BLK 1024
#define NBLK_SCAN ((NN + SCAN_BLK - 1) / SCAN_BLK)   // 98

#define CDIV(a, b) (((a) + (b) - 1) / (b))

// Scratch (static device globals; no allocation allowed)
__device__ int    g_deg[NN];
__device__ int    g_rowptr[NN + 1];
__device__ int    g_cursor[NN];
__device__ int    g_blocksums[128];
__device__ float  g_dinv[NN];
__device__ float2 g_csr[EE];        // packed (src-as-float-bits, norm) sorted by dst
__device__ float  g_h0[NN * HH];    // ping
__device__ float  g_h1[NN * HH];    // pong
__device__ float  g_t[NN * HH];     // transformed features (relu(h) @ W)

__device__ __forceinline__ float* hbuf(int s) { return s ? g_h1 : g_h0; }

// ---------------------------------------------------------------------------
// Encoder: per-node 2-layer MLP. fan_in = 3 (boundary) or 2 (interior).
// Writes relu'd h0; also zeroes the degree counter (covers all nodes).
// ---------------------------------------------------------------------------
__global__ void enc_kernel(const float* __restrict__ x, const float* __restrict__ y,
                           const int* __restrict__ idx, int n, int fan_in,
                           const float* __restrict__ W1, const float* __restrict__ b1,
                           const float* __restrict__ W2, const float* __restrict__ b2) {
    __shared__ float sW1[3 * 32], sb1[32], sW2[32 * 32], sb2[32];
    int t = threadIdx.x;
    for (int i = t; i < fan_in * 32; i += blockDim.x) sW1[i] = W1[i];
    for (int i = t; i < 32; i += blockDim.x) { sb1[i] = b1[i]; sb2[i] = b2[i]; }
    for (int i = t; i < 1024; i += blockDim.x) sW2[i] = W2[i];
    __syncthreads();

    int j = blockIdx.x * blockDim.x + t;
    if (j >= n) return;
    int node = idx[j];
    float f0 = x[2 * node], f1 = x[2 * node + 1];
    float f2 = (fan_in == 3) ? y[node] : 0.0f;

    float hid[32];
#pragma unroll
    for (int k = 0; k < 32; k++) {
        float a = f0 * sW1[k] + f1 * sW1[32 + k] + sb1[k];
        if (fan_in == 3) a += f2 * sW1[64 + k];
        hid[k] = fmaxf(a, 0.0f);
    }
    float acc[32];
#pragma unroll
    for (int jj = 0; jj < 32; jj++) acc[jj] = sb2[jj];
#pragma unroll
    for (int k = 0; k < 32; k++) {
        float hk = hid[k];
#pragma unroll
        for (int jj = 0; jj < 32; jj++) acc[jj] += hk * sW2[k * 32 + jj];
    }
    float4* hp = (float4*)&g_h0[node * HH];
#pragma unroll
    for (int q = 0; q < 8; q++) {
        hp[q] = make_float4(fmaxf(acc[4 * q + 0], 0.0f), fmaxf(acc[4 * q + 1], 0.0f),
                            fmaxf(acc[4 * q + 2], 0.0f), fmaxf(acc[4 * q + 3], 0.0f));
    }
    g_deg[node] = 0;
}

// Degree count per dst (int atomics).
__global__ void deg_kernel(const int* __restrict__ dst) {
    int e = blockIdx.x * blockDim.x + threadIdx.x;
    if (e < EE) atomicAdd(&g_deg[dst[e]], 1);
}

// dinv[i] = rsqrt(deg + 1)  (+1 = self loop)
__global__ void dinv_kernel() {
    int i = blockIdx.x * blockDim.x + threadIdx.x;
    if (i < NN) g_dinv[i] = rsqrtf((float)(g_deg[i] + 1));
}

// --- exclusive prefix sum over g_deg -> g_rowptr (3 tiny kernels) ---
__global__ void scan1_kernel() {
    __shared__ int s[SCAN_BLK];
    int tid = threadIdx.x;
    int i = blockIdx.x * SCAN_BLK + tid;
    int v = (i < NN) ? g_deg[i] : 0;
    s[tid] = v;
    __syncthreads();
#pragma unroll
    for (int off = 1; off < SCAN_BLK; off <<= 1) {
        int tmp = (tid >= off) ? s[tid - off] : 0;
        __syncthreads();
        s[tid] += tmp;
        __syncthreads();
    }
    if (i < NN) g_rowptr[i] = s[tid] - v;             // exclusive, block-local
    if (tid == SCAN_BLK - 1) g_blocksums[blockIdx.x] = s[tid];
}

__global__ void scan2_kernel() {
    __shared__ int s[128];
    int tid = threadIdx.x;
    if (tid < NBLK_SCAN) s[tid] = g_blocksums[tid];
    __syncthreads();
    if (tid == 0) {
        int run = 0;
        for (int k = 0; k < NBLK_SCAN; k++) { int v = s[k]; s[k] = run; run += v; }
    }
    __syncthreads();
    if (tid < NBLK_SCAN) g_blocksums[tid] = s[tid];
}

__global__ void scan3_kernel() {
    int i = blockIdx.x * blockDim.x + threadIdx.x;
    if (i < NN) {
        int r = g_rowptr[i] + g_blocksums[i / SCAN_BLK];
        g_rowptr[i] = r;
        g_cursor[i] = r;
    }
    if (i == 0) g_rowptr[NN] = EE;
}

// Bucket-fill CSR: csr[pos] = (src, dinv[src]*dinv[dst])
__global__ void fill_kernel(const int* __restrict__ src, const int* __restrict__ dst) {
    int e = blockIdx.x * blockDim.x + threadIdx.x;
    if (e >= EE) return;
    int s = src[e], d = dst[e];
    int pos = atomicAdd(&g_cursor[d], 1);
    g_csr[pos] = make_float2(__int_as_float(s), g_dinv[s] * g_dinv[d]);
}

// ---------------------------------------------------------------------------
// Dense transform: t[i] = relu(hin[i]) @ W   (per-node GEMV, W in smem)
// ---------------------------------------------------------------------------
__global__ void xform_kernel(int in_sel, const float* __restrict__ W) {
    __shared__ float sW[1024];
    int t = threadIdx.x;
    for (int i = t; i < 1024; i += blockDim.x) sW[i] = W[i];
    __syncthreads();

    int i = blockIdx.x * blockDim.x + t;
    if (i >= NN) return;
    const float* hin = hbuf(in_sel);

    float acc[32];
#pragma unroll
    for (int jj = 0; jj < 32; jj++) acc[jj] = 0.0f;

    const float4* hp = (const float4*)(hin + i * HH);
#pragma unroll
    for (int q = 0; q < 8; q++) {
        float4 v4 = hp[q];
        float vv[4] = {fmaxf(v4.x, 0.0f), fmaxf(v4.y, 0.0f), fmaxf(v4.z, 0.0f), fmaxf(v4.w, 0.0f)};
#pragma unroll
        for (int r = 0; r < 4; r++) {
            float v = vv[r];
            int k = 4 * q + r;
#pragma unroll
            for (int jj = 0; jj < 32; jj++) acc[jj] += v * sW[k * 32 + jj];
        }
    }
    float4* tp = (float4*)&g_t[i * HH];
#pragma unroll
    for (int q = 0; q < 8; q++)
        tp[q] = make_float4(acc[4 * q], acc[4 * q + 1], acc[4 * q + 2], acc[4 * q + 3]);
}

// ---------------------------------------------------------------------------
// Warp-per-node gather (no atomics):
//   hout[i] = b + t[i]*dinv[i]^2 + sum_{e in in(i)} t[src(e)] * norm(e)
// lane = h column; per edge: 8B broadcast read + 128B coalesced row read.
// ---------------------------------------------------------------------------
__global__ void gather_kernel(int out_sel, const float* __restrict__ b) {
    int lane = threadIdx.x & 31;
    int node = (blockIdx.x * blockDim.x + threadIdx.x) >> 5;
    if (node >= NN) return;

    float di = g_dinv[node];
    float acc = __ldg(b + lane) + g_t[node * HH + lane] * (di * di);
    float acc2 = 0.0f;

    int e = g_rowptr[node];
    int e1 = g_rowptr[node + 1];
    for (; e + 1 < e1; e += 2) {
        float2 p0 = __ldg(&g_csr[e]);
        float2 p1 = __ldg(&g_csr[e + 1]);
        acc  += __ldg(&g_t[__float_as_int(p0.x) * HH + lane]) * p0.y;
        acc2 += __ldg(&g_t[__float_as_int(p1.x) * HH + lane]) * p1.y;
    }
    if (e < e1) {
        float2 p0 = __ldg(&g_csr[e]);
        acc += __ldg(&g_t[__float_as_int(p0.x) * HH + lane]) * p0.y;
    }
    hbuf(out_sel)[node * HH + lane] = acc + acc2;
}

// Head: out[i] = dot(relu(h[i]), Wf) + bf
__global__ void final_kernel(int in_sel, const float* __restrict__ Wf,
                             const float* __restrict__ bf, float* __restrict__ out) {
    __shared__ float sw[32];
    __shared__ float sbf;
    int t = threadIdx.x;
    if (t < 32) sw[t] = Wf[t];
    if (t == 0) sbf = bf[0];
    __syncthreads();

    int i = blockIdx.x * blockDim.x + t;
    if (i >= NN) return;
    const float4* hp = (const float4*)(hbuf(in_sel) + i * HH);
    float acc = sbf;
#pragma unroll
    for (int q = 0; q < 8; q++) {
        float4 v = hp[q];
        acc += fmaxf(v.x, 0.0f) * sw[4 * q + 0];
        acc += fmaxf(v.y, 0.0f) * sw[4 * q + 1];
        acc += fmaxf(v.z, 0.0f) * sw[4 * q + 2];
        acc += fmaxf(v.w, 0.0f) * sw[4 * q + 3];
    }
    out[i] = acc;
}

extern "C" void kernel_launch(void* const* d_in, const int* in_sizes, int n_in,
                              void* d_out, int out_size) {
    const float* x    = (const float*)d_in[0];
    const float* y    = (const float*)d_in[1];
    const int*   ei   = (const int*)d_in[2];
    const int*   bidx = (const int*)d_in[3];
    const int*   iidx = (const int*)d_in[4];
    const float* Wb1 = (const float*)d_in[5];
    const float* bb1 = (const float*)d_in[6];
    const float* Wb2 = (const float*)d_in[7];
    const float* bb2 = (const float*)d_in[8];
    const float* Wi1 = (const float*)d_in[9];
    const float* bi1 = (const float*)d_in[10];
    const float* Wi2 = (const float*)d_in[11];
    const float* bi2 = (const float*)d_in[12];
    const float* Wc1 = (const float*)d_in[13];
    const float* bc1 = (const float*)d_in[14];
    const float* Wc2 = (const float*)d_in[15];
    const float* bc2 = (const float*)d_in[16];
    const float* Wc3 = (const float*)d_in[17];
    const float* bc3 = (const float*)d_in[18];
    const float* Wf  = (const float*)d_in[19];
    const float* bf  = (const float*)d_in[20];

    int NB = in_sizes[3];
    int NI = in_sizes[4];
    const int* src = ei;        // edge_index[0,:]
    const int* dst = ei + EE;   // edge_index[1,:]

    // Encoders (also zero int degree for every node)
    enc_kernel<<<CDIV(NB, 128), 128>>>(x, y, bidx, NB, 3, Wb1, bb1, Wb2, bb2);
    enc_kernel<<<CDIV(NI, 128), 128>>>(x, y, iidx, NI, 2, Wi1, bi1, Wi2, bi2);

    // CSR build: degree -> dinv -> prefix sum -> bucket fill
    deg_kernel<<<CDIV(EE, 256), 256>>>(dst);
    dinv_kernel<<<CDIV(NN, 256), 256>>>();
    scan1_kernel<<<NBLK_SCAN, SCAN_BLK>>>();
    scan2_kernel<<<1, 128>>>();
    scan3_kernel<<<CDIV(NN, 256), 256>>>();
    fill_kernel<<<CDIV(EE, 256), 256>>>(src, dst);

    // Conv 1: h0 -> h1
    xform_kernel<<<CDIV(NN, 128), 128>>>(0, Wc1);
    gather_kernel<<<CDIV(NN * 32, 256), 256>>>(1, bc1);
    // Conv 2: h1 -> h0
    xform_kernel<<<CDIV(NN, 128), 128>>>(1, Wc2);
    gather_kernel<<<CDIV(NN * 32, 256), 256>>>(0, bc2);
    // Conv 3: h0 -> h1
    xform_kernel<<<CDIV(NN, 128), 128>>>(0, Wc3);
    gather_kernel<<<CDIV(NN * 32, 256), 256>>>(1, bc3);

    // Head
    final_kernel<<<CDIV(NN, 256), 256>>>(1, Wf, bf, (float*)d_out);
}

// round 3
// speedup vs baseline: 1.3145x; 1.1342x over previous
#include <cuda_runtime.h>
#include <cuda_bf16.h>
#include <cuda_fp16.h>

// Problem constants (fixed by the dataset)
#define NN 100000
#define EE 1600000
#define HH 32
#define SCAN_BLK 1024
#define NBLK_SCAN ((NN + SCAN_BLK - 1) / SCAN_BLK)   // 98

#define CDIV(a, b) (((a) + (b) - 1) / (b))

// Scratch (static device globals; no allocation allowed)
__device__ int    g_deg[NN];
__device__ int    g_rowptr[NN + 1];
__device__ int    g_cursor[NN];
__device__ int    g_blocksums[128];
__device__ float  g_dinv[NN];
__device__ int    g_csri[EE];        // src indices, bucketed by dst
__device__ float  g_h0[NN * HH];     // ping
__device__ float  g_h1[NN * HH];     // pong
__device__ __half g_t[NN * HH];      // t'[i] = (relu(h[i]) @ W) * dinv[i], fp16

__device__ __forceinline__ float* hbuf(int s) { return s ? g_h1 : g_h0; }

// ---------------------------------------------------------------------------
// Encoder: per-node 2-layer MLP. fan_in = 3 (boundary) or 2 (interior).
// Writes relu'd h0; also zeroes the degree counter (covers all nodes).
// ---------------------------------------------------------------------------
__global__ void enc_kernel(const float* __restrict__ x, const float* __restrict__ y,
                           const int* __restrict__ idx, int n, int fan_in,
                           const float* __restrict__ W1, const float* __restrict__ b1,
                           const float* __restrict__ W2, const float* __restrict__ b2) {
    __shared__ float sW1[3 * 32], sb1[32], sW2[32 * 32], sb2[32];
    int t = threadIdx.x;
    for (int i = t; i < fan_in * 32; i += blockDim.x) sW1[i] = W1[i];
    for (int i = t; i < 32; i += blockDim.x) { sb1[i] = b1[i]; sb2[i] = b2[i]; }
    for (int i = t; i < 1024; i += blockDim.x) sW2[i] = W2[i];
    __syncthreads();

    int j = blockIdx.x * blockDim.x + t;
    if (j >= n) return;
    int node = idx[j];
    float f0 = x[2 * node], f1 = x[2 * node + 1];
    float f2 = (fan_in == 3) ? y[node] : 0.0f;

    float hid[32];
#pragma unroll
    for (int k = 0; k < 32; k++) {
        float a = f0 * sW1[k] + f1 * sW1[32 + k] + sb1[k];
        if (fan_in == 3) a += f2 * sW1[64 + k];
        hid[k] = fmaxf(a, 0.0f);
    }
    float acc[32];
#pragma unroll
    for (int jj = 0; jj < 32; jj++) acc[jj] = sb2[jj];
#pragma unroll
    for (int k = 0; k < 32; k++) {
        float hk = hid[k];
#pragma unroll
        for (int jj = 0; jj < 32; jj++) acc[jj] += hk * sW2[k * 32 + jj];
    }
    float4* hp = (float4*)&g_h0[node * HH];
#pragma unroll
    for (int q = 0; q < 8; q++) {
        hp[q] = make_float4(fmaxf(acc[4 * q + 0], 0.0f), fmaxf(acc[4 * q + 1], 0.0f),
                            fmaxf(acc[4 * q + 2], 0.0f), fmaxf(acc[4 * q + 3], 0.0f));
    }
    g_deg[node] = 0;
}

// Degree count per dst (int atomics).
__global__ void deg_kernel(const int* __restrict__ dst) {
    int e = blockIdx.x * blockDim.x + threadIdx.x;
    if (e < EE) atomicAdd(&g_deg[dst[e]], 1);
}

// dinv[i] = rsqrt(deg + 1)  (+1 = self loop)
__global__ void dinv_kernel() {
    int i = blockIdx.x * blockDim.x + threadIdx.x;
    if (i < NN) g_dinv[i] = rsqrtf((float)(g_deg[i] + 1));
}

// --- exclusive prefix sum over g_deg -> g_rowptr (3 tiny kernels) ---
__global__ void scan1_kernel() {
    __shared__ int s[SCAN_BLK];
    int tid = threadIdx.x;
    int i = blockIdx.x * SCAN_BLK + tid;
    int v = (i < NN) ? g_deg[i] : 0;
    s[tid] = v;
    __syncthreads();
#pragma unroll
    for (int off = 1; off < SCAN_BLK; off <<= 1) {
        int tmp = (tid >= off) ? s[tid - off] : 0;
        __syncthreads();
        s[tid] += tmp;
        __syncthreads();
    }
    if (i < NN) g_rowptr[i] = s[tid] - v;             // exclusive, block-local
    if (tid == SCAN_BLK - 1) g_blocksums[blockIdx.x] = s[tid];
}

__global__ void scan2_kernel() {
    __shared__ int s[128];
    int tid = threadIdx.x;
    if (tid < NBLK_SCAN) s[tid] = g_blocksums[tid];
    __syncthreads();
    if (tid == 0) {
        int run = 0;
        for (int k = 0; k < NBLK_SCAN; k++) { int v = s[k]; s[k] = run; run += v; }
    }
    __syncthreads();
    if (tid < NBLK_SCAN) g_blocksums[tid] = s[tid];
}

__global__ void scan3_kernel() {
    int i = blockIdx.x * blockDim.x + threadIdx.x;
    if (i < NN) {
        int r = g_rowptr[i] + g_blocksums[i / SCAN_BLK];
        g_rowptr[i] = r;
        g_cursor[i] = r;
    }
    if (i == 0) g_rowptr[NN] = EE;
}

// Bucket-fill CSR: only the src index (norm folded into t' and dinv[dst]).
__global__ void fill_kernel(const int* __restrict__ src, const int* __restrict__ dst) {
    int e = blockIdx.x * blockDim.x + threadIdx.x;
    if (e >= EE) return;
    int s = src[e], d = dst[e];
    int pos = atomicAdd(&g_cursor[d], 1);
    g_csri[pos] = s;
}

// ---------------------------------------------------------------------------
// Dense transform: t'[i] = (relu(hin[i]) @ W) * dinv[i], stored fp16.
// ---------------------------------------------------------------------------
__global__ void xform_kernel(int in_sel, const float* __restrict__ W) {
    __shared__ float sW[1024];
    int t = threadIdx.x;
    for (int i = t; i < 1024; i += blockDim.x) sW[i] = W[i];
    __syncthreads();

    int i = blockIdx.x * blockDim.x + t;
    if (i >= NN) return;
    const float* hin = hbuf(in_sel);

    float acc[32];
#pragma unroll
    for (int jj = 0; jj < 32; jj++) acc[jj] = 0.0f;

    const float4* hp = (const float4*)(hin + i * HH);
#pragma unroll
    for (int q = 0; q < 8; q++) {
        float4 v4 = hp[q];
        float vv[4] = {fmaxf(v4.x, 0.0f), fmaxf(v4.y, 0.0f), fmaxf(v4.z, 0.0f), fmaxf(v4.w, 0.0f)};
#pragma unroll
        for (int r = 0; r < 4; r++) {
            float v = vv[r];
            int k = 4 * q + r;
#pragma unroll
            for (int jj = 0; jj < 32; jj++) acc[jj] += v * sW[k * 32 + jj];
        }
    }
    float di = g_dinv[i];
    __half2* tp = (__half2*)&g_t[i * HH];
#pragma unroll
    for (int q = 0; q < 16; q++)
        tp[q] = __float22half2_rn(make_float2(acc[2 * q] * di, acc[2 * q + 1] * di));
}

// ---------------------------------------------------------------------------
// Subwarp (16-lane) gather, no atomics, no per-edge norm:
//   hout[i] = b + dinv[i] * ( t'[i] + sum_{e in in(i)} t'[src(e)] )
// Each lane owns 2 columns (half2). Per edge: 4B broadcast + 64B row read.
// ---------------------------------------------------------------------------
__global__ void gather_kernel(int out_sel, const float* __restrict__ b) {
    int gid = blockIdx.x * blockDim.x + threadIdx.x;
    int node = gid >> 4;
    int sub = gid & 15;
    if (node >= NN) return;

    const __half2* tp = (const __half2*)g_t;
    float2 self = __half22float2(__ldg(tp + node * 16 + sub));
    float2 acc = self, acc2 = make_float2(0.0f, 0.0f);

    int e = g_rowptr[node];
    int e1 = g_rowptr[node + 1];
    for (; e + 1 < e1; e += 2) {
        int s0 = __ldg(&g_csri[e]);
        int s1 = __ldg(&g_csri[e + 1]);
        float2 v0 = __half22float2(__ldg(tp + s0 * 16 + sub));
        float2 v1 = __half22float2(__ldg(tp + s1 * 16 + sub));
        acc.x += v0.x; acc.y += v0.y;
        acc2.x += v1.x; acc2.y += v1.y;
    }
    if (e < e1) {
        int s0 = __ldg(&g_csri[e]);
        float2 v0 = __half22float2(__ldg(tp + s0 * 16 + sub));
        acc.x += v0.x; acc.y += v0.y;
    }
    float di = g_dinv[node];
    float2 bb = __ldg((const float2*)b + sub);
    float2 outv = make_float2(bb.x + di * (acc.x + acc2.x),
                              bb.y + di * (acc.y + acc2.y));
    ((float2*)hbuf(out_sel))[node * 16 + sub] = outv;
}

// Head: out[i] = dot(relu(h[i]), Wf) + bf
__global__ void final_kernel(int in_sel, const float* __restrict__ Wf,
                             const float* __restrict__ bf, float* __restrict__ out) {
    __shared__ float sw[32];
    __shared__ float sbf;
    int t = threadIdx.x;
    if (t < 32) sw[t] = Wf[t];
    if (t == 0) sbf = bf[0];
    __syncthreads();

    int i = blockIdx.x * blockDim.x + t;
    if (i >= NN) return;
    const float4* hp = (const float4*)(hbuf(in_sel) + i * HH);
    float acc = sbf;
#pragma unroll
    for (int q = 0; q < 8; q++) {
        float4 v = hp[q];
        acc += fmaxf(v.x, 0.0f) * sw[4 * q + 0];
        acc += fmaxf(v.y, 0.0f) * sw[4 * q + 1];
        acc += fmaxf(v.z, 0.0f) * sw[4 * q + 2];
        acc += fmaxf(v.w, 0.0f) * sw[4 * q + 3];
    }
    out[i] = acc;
}

extern "C" void kernel_launch(void* const* d_in, const int* in_sizes, int n_in,
                              void* d_out, int out_size) {
    const float* x    = (const float*)d_in[0];
    const float* y    = (const float*)d_in[1];
    const int*   ei   = (const int*)d_in[2];
    const int*   bidx = (const int*)d_in[3];
    const int*   iidx = (const int*)d_in[4];
    const float* Wb1 = (const float*)d_in[5];
    const float* bb1 = (const float*)d_in[6];
    const float* Wb2 = (const float*)d_in[7];
    const float* bb2 = (const float*)d_in[8];
    const float* Wi1 = (const float*)d_in[9];
    const float* bi1 = (const float*)d_in[10];
    const float* Wi2 = (const float*)d_in[11];
    const float* bi2 = (const float*)d_in[12];
    const float* Wc1 = (const float*)d_in[13];
    const float* bc1 = (const float*)d_in[14];
    const float* Wc2 = (const float*)d_in[15];
    const float* bc2 = (const float*)d_in[16];
    const float* Wc3 = (const float*)d_in[17];
    const float* bc3 = (const float*)d_in[18];
    const float* Wf  = (const float*)d_in[19];
    const float* bf  = (const float*)d_in[20];

    int NB = in_sizes[3];
    int NI = in_sizes[4];
    const int* src = ei;        // edge_index[0,:]
    const int* dst = ei + EE;   // edge_index[1,:]

    // Encoders (also zero int degree for every node)
    enc_kernel<<<CDIV(NB, 128), 128>>>(x, y, bidx, NB, 3, Wb1, bb1, Wb2, bb2);
    enc_kernel<<<CDIV(NI, 128), 128>>>(x, y, iidx, NI, 2, Wi1, bi1, Wi2, bi2);

    // CSR build: degree -> dinv -> prefix sum -> bucket fill (index only)
    deg_kernel<<<CDIV(EE, 256), 256>>>(dst);
    dinv_kernel<<<CDIV(NN, 256), 256>>>();
    scan1_kernel<<<NBLK_SCAN, SCAN_BLK>>>();
    scan2_kernel<<<1, 128>>>();
    scan3_kernel<<<CDIV(NN, 256), 256>>>();
    fill_kernel<<<CDIV(EE, 256), 256>>>(src, dst);

    // Conv 1: h0 -> h1
    xform_kernel<<<CDIV(NN, 128), 128>>>(0, Wc1);
    gather_kernel<<<CDIV(NN * 16, 256), 256>>>(1, bc1);
    // Conv 2: h1 -> h0
    xform_kernel<<<CDIV(NN, 128), 128>>>(1, Wc2);
    gather_kernel<<<CDIV(NN * 16, 256), 256>>>(0, bc2);
    // Conv 3: h0 -> h1
    xform_kernel<<<CDIV(NN, 128), 128>>>(0, Wc3);
    gather_kernel<<<CDIV(NN * 16, 256), 256>>>(1, bc3);

    // Head
    final_kernel<<<CDIV(NN, 256), 256>>>(1, Wf, bf, (float*)d_out);
}